// round 11
// baseline (speedup 1.0000x reference)
#include <cuda_runtime.h>
#include <cuda_fp16.h>
#include <cstdint>
#include <cstddef>

// out[256,11008] = x[256,4096] @ W[11008,4096]^T * scale + bias, W ternary i32.
// fp16 mma.sync m16n8k16 single pass, fp32 accum (rel_err ~2e-4 << 1e-3).
// BM=64 BN=80 BK=64. CTA = 128 thr / 4 warps (2m x 2n), warp tile 32x40.
// 552 CTAs, 4 CTAs/SM (4 barrier domains, 4 warps/SMSP -> latency hiding).
// W: LDG.128 -> PRMT ternary->fp16 -> STS.128. A: cp.async fp16, 2 stages.
// One __syncthreads per iter.

#define M_TOK   256
#define K_DIM   4096
#define N_DIM   11008
#define BM      64
#define BN      80
#define BK      64
#define KITERS  (K_DIM / BK)          // 64
#define THREADS 128
#define N_TILES 138                   // 138*80 = 11040 >= 11008
#define GRID    (4 * N_TILES)         // 552

#define ROWB     144                  // row pad: conflict-free ldmatrix
#define A_BYTES  (BM * ROWB)          // 9216
#define B_BYTES  (BN * ROWB)          // 11520
#define A_OFF    0
#define B_OFF    (2 * A_BYTES)        // 18432
#define STAGE_A(s) ((uint32_t)((s) * A_BYTES))
#define STAGE_B(s) ((uint32_t)(B_OFF + (s) * B_BYTES))
#define SMEM_ALLOC (B_OFF + 2 * B_BYTES)   // 41472

__device__ __half g_xh[M_TOK * K_DIM];

// ---------------- asm helpers ----------------
__device__ __forceinline__ uint32_t smem_u32(const void* p) {
    uint32_t a;
    asm("{ .reg .u64 t; cvta.to.shared.u64 t, %1; cvt.u32.u64 %0, t; }"
        : "=r"(a) : "l"(p));
    return a;
}
__device__ __forceinline__ void cp16(uint32_t dst, const void* src) {
    asm volatile("cp.async.cg.shared.global [%0], [%1], 16;"
        :: "r"(dst), "l"(src) : "memory");
}
#define CP_COMMIT() asm volatile("cp.async.commit_group;" ::: "memory")
#define CP_WAIT0()  asm volatile("cp.async.wait_group 0;" ::: "memory")

__device__ __forceinline__ void ldsm4(uint32_t* r, uint32_t addr) {
    asm volatile("ldmatrix.sync.aligned.m8n8.x4.shared.b16 {%0,%1,%2,%3}, [%4];"
        : "=r"(r[0]), "=r"(r[1]), "=r"(r[2]), "=r"(r[3]) : "r"(addr));
}
__device__ __forceinline__ void ldsm2(uint32_t* r, uint32_t addr) {
    asm volatile("ldmatrix.sync.aligned.m8n8.x2.shared.b16 {%0,%1}, [%2];"
        : "=r"(r[0]), "=r"(r[1]) : "r"(addr));
}
__device__ __forceinline__ void mma_f16(float* c, const uint32_t* a,
                                        const uint32_t* b) {
    asm volatile(
        "mma.sync.aligned.m16n8k16.row.col.f32.f16.f16.f32 "
        "{%0,%1,%2,%3}, {%4,%5,%6,%7}, {%8,%9}, {%0,%1,%2,%3};"
        : "+f"(c[0]), "+f"(c[1]), "+f"(c[2]), "+f"(c[3])
        : "r"(a[0]), "r"(a[1]), "r"(a[2]), "r"(a[3]), "r"(b[0]), "r"(b[1]));
}
// two ternary int32 -> packed fp16x2 {0,+-1}: 4 ops
__device__ __forceinline__ uint32_t w2h2(uint32_t w0, uint32_t w1) {
    uint32_t c = __byte_perm(w0, w1, 0x5410);
    return ((c & 0x00010001u) * 0x3C00u) | (c & 0x80008000u);
}

// ---------------- x convert pre-kernel ----------------
__global__ void conv_x_kernel(const float* __restrict__ x) {
    int i = (blockIdx.x * blockDim.x + threadIdx.x) << 2;
    float4 v = *reinterpret_cast<const float4*>(x + i);
    __half2* ph = reinterpret_cast<__half2*>(g_xh + i);
    ph[0] = __floats2half2_rn(v.x, v.y);
    ph[1] = __floats2half2_rn(v.z, v.w);
}

// ---------------- main GEMM ----------------
__global__ void __launch_bounds__(THREADS, 4)
bitnet_gemm_kernel(const int* __restrict__ qw, const float* __restrict__ scale,
                   const float* __restrict__ bias, float* __restrict__ out) {
    extern __shared__ char smem[];
    const uint32_t su = smem_u32(smem);

    const int tid = threadIdx.x, wid = tid >> 5, lane = tid & 31;
    const int n_idx = blockIdx.x >> 2, m_idx = blockIdx.x & 3;
    const int n0 = n_idx * BN, m0 = m_idx * BM;
    const int n_sz = (n_idx == N_TILES - 1) ? (N_DIM - n0) : BN;   // 80 or 48

    const int warp_m = wid & 1;        // 2 m-groups, 32 rows each
    const int warp_n = wid >> 1;       // 2 n-groups, 40 cols each
    const int nbase = warp_n * 40;
    int ntiles = (n_sz - nbase) >> 3;
    if (ntiles > 5) ntiles = 5;
    if (ntiles < 0) ntiles = 0;
    const bool full = (ntiles == 5);

    // ldmatrix per-thread offsets (row stride 144B)
    const uint32_t a_off = (uint32_t)((warp_m * 32 + (lane & 15)) * ROWB +
                                      ((lane >> 4) << 4));
    const uint32_t b_off4 = (uint32_t)((nbase + ((lane >> 4) << 3) + (lane & 7)) * ROWB +
                                       (((lane >> 3) & 1) << 4));
    const uint32_t b_off2 = (uint32_t)((nbase + 32 + (lane & 7)) * ROWB +
                                       (((lane >> 3) & 1) << 4));

    // W LDG: thread owns kc-pair w_kp (8 int32 -> 16B fp16), rows
    // (tid>>3) + 16j, j=0..4.  2 LDG.128 + 1 STS.128 per row.
    const int w_kp = tid & 7, w_row0 = tid >> 3;
    const int* wbase = qw + (size_t)n0 * K_DIM + w_kp * 8;
    int woff[5];
#pragma unroll
    for (int j = 0; j < 5; ++j) {
        int row = w_row0 + 16 * j;
        int srow = (row < n_sz) ? row : 0;     // clamp (unread if OOB)
        woff[j] = srow * K_DIM;
    }
    // A cp.async: 512 chunks (64 rows x 8), 4/thread; rows (tid>>3)+16j
    const int a_kc = tid & 7, a_row0 = tid >> 3;
    const __half* abase = g_xh + (size_t)(m0 + a_row0) * K_DIM + a_kc * 8;
    const uint32_t ad0 = (uint32_t)(a_row0 * ROWB + a_kc * 16);

    float acc[2][5][4];
#pragma unroll
    for (int mt = 0; mt < 2; ++mt)
#pragma unroll
        for (int nt = 0; nt < 5; ++nt)
#pragma unroll
            for (int r = 0; r < 4; ++r) acc[mt][nt][r] = 0.0f;

    uint32_t wreg[40];

    auto ldgW = [&](int k0) {
#pragma unroll
        for (int j = 0; j < 5; ++j) {
            const int* s = wbase + woff[j] + k0;
            asm volatile("ld.global.cs.v4.u32 {%0,%1,%2,%3}, [%4];"
                : "=r"(wreg[8*j]),   "=r"(wreg[8*j+1]),
                  "=r"(wreg[8*j+2]), "=r"(wreg[8*j+3]) : "l"(s));
            asm volatile("ld.global.cs.v4.u32 {%0,%1,%2,%3}, [%4];"
                : "=r"(wreg[8*j+4]), "=r"(wreg[8*j+5]),
                  "=r"(wreg[8*j+6]), "=r"(wreg[8*j+7]) : "l"(s + 4));
        }
    };
    auto cpA = [&](int s, int k0) {
        const uint32_t st = su + STAGE_A(s);
#pragma unroll
        for (int j = 0; j < 4; ++j)
            cp16(st + ad0 + (uint32_t)(j * 16 * ROWB),
                 abase + (size_t)j * 16 * K_DIM + k0);
    };

    // ---- prologue ----
    ldgW(0);
    cpA(0, 0);
    CP_COMMIT();

#pragma unroll 1
    for (int it = 0; it < KITERS; ++it) {
        const int cur = it & 1;
        const uint32_t stA = su + STAGE_A(cur);
        const uint32_t stB = su + STAGE_B(cur);

        // STS W(it): 5 x STS.128 (this B buf last read by compute(it-2),
        // ordered by barrier(it-1))
#pragma unroll
        for (int j = 0; j < 5; ++j) {
            int row = w_row0 + 16 * j;
            uint32_t p0 = w2h2(wreg[8*j],   wreg[8*j+1]);
            uint32_t p1 = w2h2(wreg[8*j+2], wreg[8*j+3]);
            uint32_t p2 = w2h2(wreg[8*j+4], wreg[8*j+5]);
            uint32_t p3 = w2h2(wreg[8*j+6], wreg[8*j+7]);
            asm volatile("st.shared.v4.b32 [%0], {%1,%2,%3,%4};"
                :: "r"(stB + (uint32_t)(row * ROWB + w_kp * 16)),
                   "r"(p0), "r"(p1), "r"(p2), "r"(p3) : "memory");
        }
        if (it + 1 < KITERS) ldgW((it + 1) * BK);   // covered by compute phase
        CP_WAIT0();                                 // A(it) landed
        __syncthreads();
        if (it + 1 < KITERS) { cpA(cur ^ 1, (it + 1) * BK); CP_COMMIT(); }

        // ---- compute BK=64: 4 k16 steps ----
#pragma unroll
        for (int ks = 0; ks < 4; ++ks) {
            const uint32_t ksb = (uint32_t)(ks * 32);
            uint32_t b[5][2];
            if (full) {
                ldsm4(&b[0][0], stB + b_off4 + ksb);
                ldsm4(&b[2][0], stB + b_off4 + 16 * ROWB + ksb);
                ldsm2(&b[4][0], stB + b_off2 + ksb);
            } else {
#pragma unroll
                for (int nt = 0; nt < 5; ++nt)
                    if (nt < ntiles)
                        ldsm2(&b[nt][0], stB +
                              (uint32_t)((nbase + nt * 8 + (lane & 7)) * ROWB +
                                         (((lane >> 3) & 1) << 4)) + ksb);
            }
            uint32_t a[2][4];
#pragma unroll
            for (int mt = 0; mt < 2; ++mt)
                ldsm4(a[mt], stA + a_off + (uint32_t)(mt * 16 * ROWB) + ksb);
#pragma unroll
            for (int mt = 0; mt < 2; ++mt)
#pragma unroll
                for (int nt = 0; nt < 5; ++nt)
                    if (nt < ntiles) mma_f16(acc[mt][nt], a[mt], b[nt]);
        }
    }

    // ---- epilogue: scale/bias + store ----
    const int row_base = m0 + warp_m * 32 + (lane >> 2);
    const int col_base = n0 + nbase + ((lane & 3) << 1);
#pragma unroll
    for (int mt = 0; mt < 2; ++mt) {
#pragma unroll
        for (int nt = 0; nt < 5; ++nt) {
            if (nt < ntiles) {
                int col = col_base + nt * 8;
                float2 sc = *reinterpret_cast<const float2*>(scale + col);
                float2 bs = *reinterpret_cast<const float2*>(bias + col);
                int r0 = row_base + mt * 16;
                float2 o0, o1;
                o0.x = acc[mt][nt][0] * sc.x + bs.x;
                o0.y = acc[mt][nt][1] * sc.y + bs.y;
                o1.x = acc[mt][nt][2] * sc.x + bs.x;
                o1.y = acc[mt][nt][3] * sc.y + bs.y;
                *reinterpret_cast<float2*>(out + (size_t)r0 * N_DIM + col) = o0;
                *reinterpret_cast<float2*>(out + (size_t)(r0 + 8) * N_DIM + col) = o1;
            }
        }
    }
}

// ---------------- launch ----------------
extern "C" void kernel_launch(void* const* d_in, const int* in_sizes, int n_in,
                              void* d_out, int out_size) {
    const float* x = nullptr; const int* qw = nullptr;
    const float* scale = nullptr; const float* bias = nullptr;
    for (int i = 0; i < n_in; ++i) {
        if (in_sizes[i] == M_TOK * K_DIM) x = (const float*)d_in[i];
        else if (in_sizes[i] == N_DIM * K_DIM) qw = (const int*)d_in[i];
        else if (in_sizes[i] == N_DIM) {
            if (!scale) scale = (const float*)d_in[i];
            else bias = (const float*)d_in[i];
        }
    }
    float* out = (float*)d_out;

    cudaFuncSetAttribute(bitnet_gemm_kernel,
                         cudaFuncAttributeMaxDynamicSharedMemorySize, SMEM_ALLOC);

    conv_x_kernel<<<(M_TOK * K_DIM) / (256 * 4), 256>>>(x);
    bitnet_gemm_kernel<<<GRID, THREADS, SMEM_ALLOC>>>(qw, scale, bias, out);
}

// round 12
// speedup vs baseline: 1.2135x; 1.2135x over previous
#include <cuda_runtime.h>
#include <cuda_fp16.h>
#include <cstdint>
#include <cstddef>

// out[256,11008] = x[256,4096] @ W[11008,4096]^T * scale + bias, W ternary i32.
// fp16 mma.sync m16n8k16 single pass, fp32 accum (rel_err ~2e-4 << 1e-3).
// BM=128 BN=80 BK=64, CTA = 128 thr / 4 warps (2m x 2n), warp tile 64x40,
// 276 CTAs, 2 CTAs/SM.
// KEY CHANGE vs R8: A never touches SMEM. Pre-kernel writes x in mma
// A-fragment order (16x16 frag = 32 lanes x 16B contiguous); GEMM loads A
// frags with coalesced LDG.128 into regs. Removes cpA + A-ldsm wavefronts
// (-24% L1 traffic); barrier only orders the B STS.
// B: W LDG.128 -> PRMT ternary->fp16 -> STS.128 -> ldsm.

#define M_TOK   256
#define K_DIM   4096
#define N_DIM   11008
#define BM      128
#define BN      80
#define BK      64
#define KITERS  (K_DIM / BK)          // 64
#define THREADS 128
#define N_TILES 138                   // 138*80 = 11040 >= 11008
#define GRID    (2 * N_TILES)         // 276

#define ROWB    144                   // B row pad: conflict-free ldmatrix
#define B_BYTES (BN * ROWB)           // 11520
#define SMEM_ALLOC (2 * B_BYTES)      // 23040

#define N_TM    (M_TOK / 16)          // 16 m-frag rows
#define N_KS    (K_DIM / 16)          // 256 k16 chunks

// x in A-fragment order: [tm][ks][lane] of uint4 (16B per lane)
__device__ uint4 g_xa[N_TM * N_KS * 32];

// ---------------- asm helpers ----------------
__device__ __forceinline__ uint32_t smem_u32(const void* p) {
    uint32_t a;
    asm("{ .reg .u64 t; cvta.to.shared.u64 t, %1; cvt.u32.u64 %0, t; }"
        : "=r"(a) : "l"(p));
    return a;
}
__device__ __forceinline__ void ldsm4(uint32_t* r, uint32_t addr) {
    asm volatile("ldmatrix.sync.aligned.m8n8.x4.shared.b16 {%0,%1,%2,%3}, [%4];"
        : "=r"(r[0]), "=r"(r[1]), "=r"(r[2]), "=r"(r[3]) : "r"(addr));
}
__device__ __forceinline__ void ldsm2(uint32_t* r, uint32_t addr) {
    asm volatile("ldmatrix.sync.aligned.m8n8.x2.shared.b16 {%0,%1}, [%2];"
        : "=r"(r[0]), "=r"(r[1]) : "r"(addr));
}
__device__ __forceinline__ void mma_f16(float* c, const uint32_t* a,
                                        const uint32_t* b) {
    asm volatile(
        "mma.sync.aligned.m16n8k16.row.col.f32.f16.f16.f32 "
        "{%0,%1,%2,%3}, {%4,%5,%6,%7}, {%8,%9}, {%0,%1,%2,%3};"
        : "+f"(c[0]), "+f"(c[1]), "+f"(c[2]), "+f"(c[3])
        : "r"(a[0]), "r"(a[1]), "r"(a[2]), "r"(a[3]), "r"(b[0]), "r"(b[1]));
}
// two ternary int32 -> packed fp16x2 {0,+-1}: 4 ops
__device__ __forceinline__ uint32_t w2h2(uint32_t w0, uint32_t w1) {
    uint32_t c = __byte_perm(w0, w1, 0x5410);
    return ((c & 0x00010001u) * 0x3C00u) | (c & 0x80008000u);
}
__device__ __forceinline__ uint32_t h2u(float a, float b) {
    __half2 h = __floats2half2_rn(a, b);
    return *reinterpret_cast<uint32_t*>(&h);
}

// ---------------- x -> A-fragment pre-kernel ----------------
// frag (tm, ks): 16 rows [tm*16, +16), 16 k [ks*16, +16). Lane layout matches
// ldmatrix.x4 result / mma.sync A operand:
//   R0={A[r][c],A[r][c+1]} R1={A[r+8][c],..} R2={A[r][c+8],..} R3={A[r+8][c+8],..}
//   with r = tm*16 + lane/4, c = ks*16 + (lane%4)*2
__global__ void conv_x_frag(const float* __restrict__ x) {
    int gt = blockIdx.x * blockDim.x + threadIdx.x;
    int fid = gt >> 5, lane = gt & 31;
    int tm = fid >> 8, ks = fid & 255;
    int r = tm * 16 + (lane >> 2);
    int c = ks * 16 + ((lane & 3) << 1);
    const float* p0 = x + (size_t)r * K_DIM + c;
    const float* p1 = p0 + 8 * K_DIM;
    float2 v00 = *reinterpret_cast<const float2*>(p0);
    float2 v01 = *reinterpret_cast<const float2*>(p0 + 8);
    float2 v10 = *reinterpret_cast<const float2*>(p1);
    float2 v11 = *reinterpret_cast<const float2*>(p1 + 8);
    uint4 o;
    o.x = h2u(v00.x, v00.y);
    o.y = h2u(v10.x, v10.y);
    o.z = h2u(v01.x, v01.y);
    o.w = h2u(v11.x, v11.y);
    g_xa[fid * 32 + lane] = o;
}

// ---------------- main GEMM ----------------
__global__ void __launch_bounds__(THREADS, 2)
bitnet_gemm_kernel(const int* __restrict__ qw, const float* __restrict__ scale,
                   const float* __restrict__ bias, float* __restrict__ out) {
    extern __shared__ char smem[];
    const uint32_t su = smem_u32(smem);

    const int tid = threadIdx.x, wid = tid >> 5, lane = tid & 31;
    const int n_idx = blockIdx.x >> 1, m_idx = blockIdx.x & 1;
    const int n0 = n_idx * BN;
    const int n_sz = (n_idx == N_TILES - 1) ? (N_DIM - n0) : BN;   // 80 or 48

    const int warp_m = wid & 1;        // 2 m-groups, 64 rows each
    const int warp_n = wid >> 1;       // 2 n-groups, 40 cols each
    const int nbase = warp_n * 40;
    int ntiles = (n_sz - nbase) >> 3;
    if (ntiles > 5) ntiles = 5;
    if (ntiles < 0) ntiles = 0;
    const bool full = (ntiles == 5);

    // B ldmatrix offsets (row stride 144B)
    const uint32_t b_off4 = (uint32_t)((nbase + ((lane >> 4) << 3) + (lane & 7)) * ROWB +
                                       (((lane >> 3) & 1) << 4));
    const uint32_t b_off2 = (uint32_t)((nbase + 32 + (lane & 7)) * ROWB +
                                       (((lane >> 3) & 1) << 4));

    // A frag base: tm rows for this warp = m_idx*8 + warp_m*4 + mt
    const uint4* gxa = g_xa +
        ((size_t)(m_idx * 8 + warp_m * 4) * N_KS) * 32 + lane;

    // W LDG: thread owns kc-pair w_kp (8 int32 -> 16B fp16), rows
    // (tid>>3) + 16j, j=0..4.  2 LDG.128 + 1 STS.128 per row.
    const int w_kp = tid & 7, w_row0 = tid >> 3;
    const int* wbase = qw + (size_t)n0 * K_DIM + w_kp * 8;
    int woff[5];
#pragma unroll
    for (int j = 0; j < 5; ++j) {
        int row = w_row0 + 16 * j;
        int srow = (row < n_sz) ? row : 0;     // clamp (unread if OOB)
        woff[j] = srow * K_DIM;
    }

    float acc[4][5][4];
#pragma unroll
    for (int mt = 0; mt < 4; ++mt)
#pragma unroll
        for (int nt = 0; nt < 5; ++nt)
#pragma unroll
            for (int r = 0; r < 4; ++r) acc[mt][nt][r] = 0.0f;

    uint32_t wreg[40];

    auto ldgW = [&](int k0) {
#pragma unroll
        for (int j = 0; j < 5; ++j) {
            const int* s = wbase + woff[j] + k0;
            asm volatile("ld.global.cs.v4.u32 {%0,%1,%2,%3}, [%4];"
                : "=r"(wreg[8*j]),   "=r"(wreg[8*j+1]),
                  "=r"(wreg[8*j+2]), "=r"(wreg[8*j+3]) : "l"(s));
            asm volatile("ld.global.cs.v4.u32 {%0,%1,%2,%3}, [%4];"
                : "=r"(wreg[8*j+4]), "=r"(wreg[8*j+5]),
                  "=r"(wreg[8*j+6]), "=r"(wreg[8*j+7]) : "l"(s + 4));
        }
    };

    // ---- prologue ----
    ldgW(0);

#pragma unroll 1
    for (int it = 0; it < KITERS; ++it) {
        const uint32_t stB = su + (uint32_t)((it & 1) * B_BYTES);

        // STS W(it): 5 x STS.128 (this B buf last read by compute(it-2),
        // ordered by barrier(it-1))
#pragma unroll
        for (int j = 0; j < 5; ++j) {
            int row = w_row0 + 16 * j;
            uint32_t p0 = w2h2(wreg[8*j],   wreg[8*j+1]);
            uint32_t p1 = w2h2(wreg[8*j+2], wreg[8*j+3]);
            uint32_t p2 = w2h2(wreg[8*j+4], wreg[8*j+5]);
            uint32_t p3 = w2h2(wreg[8*j+6], wreg[8*j+7]);
            asm volatile("st.shared.v4.b32 [%0], {%1,%2,%3,%4};"
                :: "r"(stB + (uint32_t)(row * ROWB + w_kp * 16)),
                   "r"(p0), "r"(p1), "r"(p2), "r"(p3) : "memory");
        }
        if (it + 1 < KITERS) ldgW((it + 1) * BK);   // covered by compute phase

        // A frags for this iter: 16 coalesced LDG.128 (no SMEM, no barrier
        // dependency) — issued pre-barrier so they overlap barrier wait.
        uint4 av[4][4];                              // [ks][mt]
        {
            const int ksg = it * 4;
#pragma unroll
            for (int ks = 0; ks < 4; ++ks)
#pragma unroll
                for (int mt = 0; mt < 4; ++mt)
                    av[ks][mt] = __ldg(gxa + ((size_t)mt * N_KS + ksg + ks) * 32);
        }

        __syncthreads();                             // B buf(it) visible

        // ---- compute BK=64: 4 k16 steps ----
#pragma unroll
        for (int ks = 0; ks < 4; ++ks) {
            const uint32_t ksb = (uint32_t)(ks * 32);
            uint32_t b[5][2];
            if (full) {
                ldsm4(&b[0][0], stB + b_off4 + ksb);
                ldsm4(&b[2][0], stB + b_off4 + 16 * ROWB + ksb);
                ldsm2(&b[4][0], stB + b_off2 + ksb);
            } else {
#pragma unroll
                for (int nt = 0; nt < 5; ++nt)
                    if (nt < ntiles)
                        ldsm2(&b[nt][0], stB +
                              (uint32_t)((nbase + nt * 8 + (lane & 7)) * ROWB +
                                         (((lane >> 3) & 1) << 4)) + ksb);
            }
#pragma unroll
            for (int mt = 0; mt < 4; ++mt)
#pragma unroll
                for (int nt = 0; nt < 5; ++nt)
                    if (nt < ntiles)
                        mma_f16(acc[mt][nt],
                                reinterpret_cast<const uint32_t*>(&av[ks][mt]),
                                b[nt]);
        }
        // next iter's STS targets the other B buf; barrier above ordered
        // compute(it-1) before it.
    }

    // ---- epilogue: scale/bias + store ----
    const int row_base = m_idx * BM + warp_m * 64 + (lane >> 2);
    const int col_base = n0 + nbase + ((lane & 3) << 1);
#pragma unroll
    for (int mt = 0; mt < 4; ++mt) {
#pragma unroll
        for (int nt = 0; nt < 5; ++nt) {
            if (nt < ntiles) {
                int col = col_base + nt * 8;
                float2 sc = *reinterpret_cast<const float2*>(scale + col);
                float2 bs = *reinterpret_cast<const float2*>(bias + col);
                int r0 = row_base + mt * 16;
                float2 o0, o1;
                o0.x = acc[mt][nt][0] * sc.x + bs.x;
                o0.y = acc[mt][nt][1] * sc.y + bs.y;
                o1.x = acc[mt][nt][2] * sc.x + bs.x;
                o1.y = acc[mt][nt][3] * sc.y + bs.y;
                *reinterpret_cast<float2*>(out + (size_t)r0 * N_DIM + col) = o0;
                *reinterpret_cast<float2*>(out + (size_t)(r0 + 8) * N_DIM + col) = o1;
            }
        }
    }
}

// ---------------- launch ----------------
extern "C" void kernel_launch(void* const* d_in, const int* in_sizes, int n_in,
                              void* d_out, int out_size) {
    const float* x = nullptr; const int* qw = nullptr;
    const float* scale = nullptr; const float* bias = nullptr;
    for (int i = 0; i < n_in; ++i) {
        if (in_sizes[i] == M_TOK * K_DIM) x = (const float*)d_in[i];
        else if (in_sizes[i] == N_DIM * K_DIM) qw = (const int*)d_in[i];
        else if (in_sizes[i] == N_DIM) {
            if (!scale) scale = (const float*)d_in[i];
            else bias = (const float*)d_in[i];
        }
    }
    float* out = (float*)d_out;

    cudaFuncSetAttribute(bitnet_gemm_kernel,
                         cudaFuncAttributeMaxDynamicSharedMemorySize, SMEM_ALLOC);

    // 16*256 frags, one warp each: 131072 threads
    conv_x_frag<<<(N_TM * N_KS * 32) / 128, 128>>>(x);
    bitnet_gemm_kernel<<<GRID, THREADS, SMEM_ALLOC>>>(qw, scale, bias, out);
}

// round 13
// speedup vs baseline: 1.2254x; 1.0099x over previous
#include <cuda_runtime.h>
#include <cuda_fp16.h>
#include <cstdint>
#include <cstddef>

// out[256,11008] = x[256,4096] @ W[11008,4096]^T * scale + bias, W ternary i32.
// fp16 mma.sync m16n8k16 single pass, fp32 accum (rel_err ~2e-4 << 1e-3).
// WARP-SPECIALIZED: 4 producer warps (W LDG -> PRMT -> STS; A cp.async) feed a
// 3-stage SMEM ring; 8 consumer warps (2n x 4m, warp tile 64x40) do only
// ldsm + HMMA. Named-barrier full/free semaphores decouple the phases.
// BM=256 (full M). Mixed BN: 96 CTAs x 80 + 52 x 64 = 11008 -> 148 CTAs,
// one wave, W streamed exactly once.

#define M_TOK   256
#define K_DIM   4096
#define N_DIM   11008
#define BK      64
#define KITERS  (K_DIM / BK)          // 64
#define THREADS 384                   // 8 consumer + 4 producer warps
#define GRID    148
#define RING    3

#define ROWB    144
#define A_BYTES (256 * ROWB)          // 36864
#define B_BYTES (80 * ROWB)           // 11520 (max BN)
#define STG     (A_BYTES + B_BYTES)   // 48384
#define SMEM_ALLOC (RING * STG)       // 145152

// named barrier ids: 1..3 = full[s], 4..6 = free[s]
#define FULL0 1
#define FREE0 4

__device__ __half g_xh[M_TOK * K_DIM];

// ---------------- asm helpers ----------------
__device__ __forceinline__ uint32_t smem_u32(const void* p) {
    uint32_t a;
    asm("{ .reg .u64 t; cvta.to.shared.u64 t, %1; cvt.u32.u64 %0, t; }"
        : "=r"(a) : "l"(p));
    return a;
}
__device__ __forceinline__ void bar_sync_named(int id) {
    asm volatile("bar.sync %0, 384;" :: "r"(id) : "memory");
}
__device__ __forceinline__ void bar_arrive_named(int id) {
    asm volatile("bar.arrive %0, 384;" :: "r"(id) : "memory");
}
__device__ __forceinline__ void cp16(uint32_t dst, const void* src) {
    asm volatile("cp.async.cg.shared.global [%0], [%1], 16;"
        :: "r"(dst), "l"(src) : "memory");
}
#define CP_COMMIT() asm volatile("cp.async.commit_group;" ::: "memory")
#define CP_WAIT0()  asm volatile("cp.async.wait_group 0;" ::: "memory")

__device__ __forceinline__ void ldsm4(uint32_t* r, uint32_t addr) {
    asm volatile("ldmatrix.sync.aligned.m8n8.x4.shared.b16 {%0,%1,%2,%3}, [%4];"
        : "=r"(r[0]), "=r"(r[1]), "=r"(r[2]), "=r"(r[3]) : "r"(addr));
}
__device__ __forceinline__ void ldsm2(uint32_t* r, uint32_t addr) {
    asm volatile("ldmatrix.sync.aligned.m8n8.x2.shared.b16 {%0,%1}, [%2];"
        : "=r"(r[0]), "=r"(r[1]) : "r"(addr));
}
__device__ __forceinline__ void mma_f16(float* c, const uint32_t* a,
                                        const uint32_t* b) {
    asm volatile(
        "mma.sync.aligned.m16n8k16.row.col.f32.f16.f16.f32 "
        "{%0,%1,%2,%3}, {%4,%5,%6,%7}, {%8,%9}, {%0,%1,%2,%3};"
        : "+f"(c[0]), "+f"(c[1]), "+f"(c[2]), "+f"(c[3])
        : "r"(a[0]), "r"(a[1]), "r"(a[2]), "r"(a[3]), "r"(b[0]), "r"(b[1]));
}
__device__ __forceinline__ uint32_t w2h2(uint32_t w0, uint32_t w1) {
    uint32_t c = __byte_perm(w0, w1, 0x5410);
    return ((c & 0x00010001u) * 0x3C00u) | (c & 0x80008000u);
}

// ---------------- x convert pre-kernel ----------------
__global__ void conv_x_kernel(const float* __restrict__ x) {
    int i = (blockIdx.x * blockDim.x + threadIdx.x) << 2;
    float4 v = *reinterpret_cast<const float4*>(x + i);
    __half2* ph = reinterpret_cast<__half2*>(g_xh + i);
    ph[0] = __floats2half2_rn(v.x, v.y);
    ph[1] = __floats2half2_rn(v.z, v.w);
}

// ---------------- main GEMM ----------------
__global__ void __launch_bounds__(THREADS, 1)
bitnet_gemm_kernel(const int* __restrict__ qw, const float* __restrict__ scale,
                   const float* __restrict__ bias, float* __restrict__ out) {
    extern __shared__ char smem[];
    const uint32_t su = smem_u32(smem);

    const int tid = threadIdx.x, wid = tid >> 5, lane = tid & 31;
    const int cta = blockIdx.x;
    int n0, n_sz;
    if (cta < 96) { n0 = cta * 80; n_sz = 80; }
    else          { n0 = 7680 + (cta - 96) * 64; n_sz = 64; }

    if (wid >= 8) {
        // ================= PRODUCER (warps 8-11, 128 threads) =================
        const int ptid = tid - 256;
        // W: rows w_row0+16j (j<nWr), kc-pair w_kp (8 ints -> 16B fp16)
        const int w_kp = ptid & 7, w_row0 = ptid >> 3;
        const int nWr = n_sz >> 4;                 // 5 (BN=80) or 4 (BN=64)
        const int* wbase = qw + (size_t)n0 * K_DIM + w_kp * 8;
        int woff[5];
#pragma unroll
        for (int j = 0; j < 5; ++j) woff[j] = (w_row0 + 16 * j) * K_DIM;
        // A: rows a_row0+16j (j<16), kc a_kc
        const int a_kc = ptid & 7, a_row0 = ptid >> 3;
        const __half* abase = g_xh + (size_t)a_row0 * K_DIM + a_kc * 8;
        const uint32_t ad0 = (uint32_t)(a_row0 * ROWB + a_kc * 16);

        uint32_t wreg[40];
        auto ldgW = [&](int k0) {
#pragma unroll
            for (int j = 0; j < 5; ++j) {
                if (j < nWr) {
                    const int* s = wbase + woff[j] + k0;
                    asm volatile("ld.global.cs.v4.u32 {%0,%1,%2,%3}, [%4];"
                        : "=r"(wreg[8*j]),   "=r"(wreg[8*j+1]),
                          "=r"(wreg[8*j+2]), "=r"(wreg[8*j+3]) : "l"(s));
                    asm volatile("ld.global.cs.v4.u32 {%0,%1,%2,%3}, [%4];"
                        : "=r"(wreg[8*j+4]), "=r"(wreg[8*j+5]),
                          "=r"(wreg[8*j+6]), "=r"(wreg[8*j+7]) : "l"(s + 4));
                }
            }
        };

        ldgW(0);
#pragma unroll 1
        for (int k = 0; k < KITERS; ++k) {
            const int s = k % RING;
            if (k >= RING) bar_sync_named(FREE0 + s);   // stage free
            const uint32_t st = su + (uint32_t)(s * STG);
            // A(k): 16 cp.async chunks
#pragma unroll
            for (int j = 0; j < 16; ++j)
                cp16(st + ad0 + (uint32_t)(j * 16 * ROWB),
                     abase + (size_t)j * 16 * K_DIM + k * BK);
            CP_COMMIT();
            // W(k): convert + STS.128
            const uint32_t stB = st + A_BYTES;
#pragma unroll
            for (int j = 0; j < 5; ++j) {
                if (j < nWr) {
                    uint32_t p0 = w2h2(wreg[8*j],   wreg[8*j+1]);
                    uint32_t p1 = w2h2(wreg[8*j+2], wreg[8*j+3]);
                    uint32_t p2 = w2h2(wreg[8*j+4], wreg[8*j+5]);
                    uint32_t p3 = w2h2(wreg[8*j+6], wreg[8*j+7]);
                    asm volatile("st.shared.v4.b32 [%0], {%1,%2,%3,%4};"
                        :: "r"(stB + (uint32_t)((w_row0 + 16*j) * ROWB + w_kp * 16)),
                           "r"(p0), "r"(p1), "r"(p2), "r"(p3) : "memory");
                }
            }
            if (k + 1 < KITERS) ldgW((k + 1) * BK);    // prefetch next W
            CP_WAIT0();                                 // A(k) landed
            __threadfence_block();                      // order STS before arrive
            bar_arrive_named(FULL0 + s);                // stage full
        }
    } else {
        // ================= CONSUMER (warps 0-7, 256 threads) =================
        const int warp_m = wid & 3;        // 4 m-groups, 64 rows each
        const int warp_n = wid >> 2;       // 2 n-groups, 40 cols each
        const int nbase = warp_n * 40;
        int ntiles = (n_sz - nbase) >> 3;
        if (ntiles > 5) ntiles = 5;
        if (ntiles < 0) ntiles = 0;
        const bool full = (ntiles == 5);

        const uint32_t a_off = (uint32_t)((warp_m * 64 + (lane & 15)) * ROWB +
                                          ((lane >> 4) << 4));
        const uint32_t b_off4 = (uint32_t)((nbase + ((lane >> 4) << 3) + (lane & 7)) * ROWB +
                                           (((lane >> 3) & 1) << 4));
        const uint32_t b_off2 = (uint32_t)((nbase + 32 + (lane & 7)) * ROWB +
                                           (((lane >> 3) & 1) << 4));

        float acc[4][5][4];
#pragma unroll
        for (int mt = 0; mt < 4; ++mt)
#pragma unroll
            for (int nt = 0; nt < 5; ++nt)
#pragma unroll
                for (int r = 0; r < 4; ++r) acc[mt][nt][r] = 0.0f;

#pragma unroll 1
        for (int k = 0; k < KITERS; ++k) {
            const int s = k % RING;
            bar_sync_named(FULL0 + s);                  // wait stage filled
            const uint32_t stA = su + (uint32_t)(s * STG);
            const uint32_t stB = stA + A_BYTES;
#pragma unroll
            for (int ks = 0; ks < 4; ++ks) {
                const uint32_t ksb = (uint32_t)(ks * 32);
                uint32_t b[5][2];
                if (full) {
                    ldsm4(&b[0][0], stB + b_off4 + ksb);
                    ldsm4(&b[2][0], stB + b_off4 + 16 * ROWB + ksb);
                    ldsm2(&b[4][0], stB + b_off2 + ksb);
                } else {
#pragma unroll
                    for (int nt = 0; nt < 5; ++nt)
                        if (nt < ntiles)
                            ldsm2(&b[nt][0], stB +
                                  (uint32_t)((nbase + nt * 8 + (lane & 7)) * ROWB +
                                             (((lane >> 3) & 1) << 4)) + ksb);
                }
                uint32_t a[4][4];
#pragma unroll
                for (int mt = 0; mt < 4; ++mt)
                    ldsm4(a[mt], stA + a_off + (uint32_t)(mt * 16 * ROWB) + ksb);
#pragma unroll
                for (int mt = 0; mt < 4; ++mt)
#pragma unroll
                    for (int nt = 0; nt < 5; ++nt)
                        if (nt < ntiles) mma_f16(acc[mt][nt], a[mt], b[nt]);
            }
            if (k < KITERS - RING) bar_arrive_named(FREE0 + s);  // release stage
        }

        // ---- epilogue: scale/bias + store ----
        const int row_base = warp_m * 64 + (lane >> 2);
        const int col_base = n0 + nbase + ((lane & 3) << 1);
#pragma unroll
        for (int mt = 0; mt < 4; ++mt) {
#pragma unroll
            for (int nt = 0; nt < 5; ++nt) {
                if (nt < ntiles) {
                    int col = col_base + nt * 8;
                    float2 sc = *reinterpret_cast<const float2*>(scale + col);
                    float2 bs = *reinterpret_cast<const float2*>(bias + col);
                    int r0 = row_base + mt * 16;
                    float2 o0, o1;
                    o0.x = acc[mt][nt][0] * sc.x + bs.x;
                    o0.y = acc[mt][nt][1] * sc.y + bs.y;
                    o1.x = acc[mt][nt][2] * sc.x + bs.x;
                    o1.y = acc[mt][nt][3] * sc.y + bs.y;
                    *reinterpret_cast<float2*>(out + (size_t)r0 * N_DIM + col) = o0;
                    *reinterpret_cast<float2*>(out + (size_t)(r0 + 8) * N_DIM + col) = o1;
                }
            }
        }
    }
}

// ---------------- launch ----------------
extern "C" void kernel_launch(void* const* d_in, const int* in_sizes, int n_in,
                              void* d_out, int out_size) {
    const float* x = nullptr; const int* qw = nullptr;
    const float* scale = nullptr; const float* bias = nullptr;
    for (int i = 0; i < n_in; ++i) {
        if (in_sizes[i] == M_TOK * K_DIM) x = (const float*)d_in[i];
        else if (in_sizes[i] == N_DIM * K_DIM) qw = (const int*)d_in[i];
        else if (in_sizes[i] == N_DIM) {
            if (!scale) scale = (const float*)d_in[i];
            else bias = (const float*)d_in[i];
        }
    }
    float* out = (float*)d_out;

    cudaFuncSetAttribute(bitnet_gemm_kernel,
                         cudaFuncAttributeMaxDynamicSharedMemorySize, SMEM_ALLOC);

    conv_x_kernel<<<(M_TOK * K_DIM) / (256 * 4), 256>>>(x);
    bitnet_gemm_kernel<<<GRID, THREADS, SMEM_ALLOC>>>(qw, scale, bias, out);
}

// round 14
// speedup vs baseline: 1.2258x; 1.0003x over previous
#include <cuda_runtime.h>
#include <cuda_fp16.h>
#include <cstdint>
#include <cstddef>

// out[256,11008] = x[256,4096] @ W[11008,4096]^T * scale + bias, W ternary i32.
// fp16 mma.sync m16n8k16 single pass, fp32 accum (rel_err ~2e-4 << 1e-3).
// WARP-SPECIALIZED + SOFTWARE-PIPELINED CONSUMER:
//   4 producer warps: W LDG -> PRMT -> STS; A cp.async; 3-stage SMEM ring.
//   8 consumer warps (2n x 4m, warp tile 64x40): frag double-buffer — LDSM of
//   step ks+1 issued before HMMAs of ks; FULL-wait for stage k+1 hoisted into
//   iter k so the tensor stream never drains at iteration boundaries.
// BM=256 (full M). Mixed BN: 96 x 80 + 52 x 64 = 11008 -> 148 CTAs, one wave.

#define M_TOK   256
#define K_DIM   4096
#define N_DIM   11008
#define BK      64
#define KITERS  (K_DIM / BK)          // 64
#define THREADS 384                   // 8 consumer + 4 producer warps
#define GRID    148
#define RING    3

#define ROWB    144
#define A_BYTES (256 * ROWB)          // 36864
#define B_BYTES (80 * ROWB)           // 11520 (max BN)
#define STG     (A_BYTES + B_BYTES)   // 48384
#define SMEM_ALLOC (RING * STG)       // 145152

// named barrier ids: 1..3 = full[s], 4..6 = free[s]
#define FULL0 1
#define FREE0 4

__device__ __half g_xh[M_TOK * K_DIM];

// ---------------- asm helpers ----------------
__device__ __forceinline__ uint32_t smem_u32(const void* p) {
    uint32_t a;
    asm("{ .reg .u64 t; cvta.to.shared.u64 t, %1; cvt.u32.u64 %0, t; }"
        : "=r"(a) : "l"(p));
    return a;
}
__device__ __forceinline__ void bar_sync_named(int id) {
    asm volatile("bar.sync %0, 384;" :: "r"(id) : "memory");
}
__device__ __forceinline__ void bar_arrive_named(int id) {
    asm volatile("bar.arrive %0, 384;" :: "r"(id) : "memory");
}
__device__ __forceinline__ void cp16(uint32_t dst, const void* src) {
    asm volatile("cp.async.cg.shared.global [%0], [%1], 16;"
        :: "r"(dst), "l"(src) : "memory");
}
#define CP_COMMIT() asm volatile("cp.async.commit_group;" ::: "memory")
#define CP_WAIT0()  asm volatile("cp.async.wait_group 0;" ::: "memory")

__device__ __forceinline__ void ldsm4(uint32_t* r, uint32_t addr) {
    asm volatile("ldmatrix.sync.aligned.m8n8.x4.shared.b16 {%0,%1,%2,%3}, [%4];"
        : "=r"(r[0]), "=r"(r[1]), "=r"(r[2]), "=r"(r[3]) : "r"(addr));
}
__device__ __forceinline__ void ldsm2(uint32_t* r, uint32_t addr) {
    asm volatile("ldmatrix.sync.aligned.m8n8.x2.shared.b16 {%0,%1}, [%2];"
        : "=r"(r[0]), "=r"(r[1]) : "r"(addr));
}
__device__ __forceinline__ void mma_f16(float* c, const uint32_t* a,
                                        const uint32_t* b) {
    asm volatile(
        "mma.sync.aligned.m16n8k16.row.col.f32.f16.f16.f32 "
        "{%0,%1,%2,%3}, {%4,%5,%6,%7}, {%8,%9}, {%0,%1,%2,%3};"
        : "+f"(c[0]), "+f"(c[1]), "+f"(c[2]), "+f"(c[3])
        : "r"(a[0]), "r"(a[1]), "r"(a[2]), "r"(a[3]), "r"(b[0]), "r"(b[1]));
}
__device__ __forceinline__ uint32_t w2h2(uint32_t w0, uint32_t w1) {
    uint32_t c = __byte_perm(w0, w1, 0x5410);
    return ((c & 0x00010001u) * 0x3C00u) | (c & 0x80008000u);
}

// ---------------- x convert pre-kernel ----------------
__global__ void conv_x_kernel(const float* __restrict__ x) {
    int i = (blockIdx.x * blockDim.x + threadIdx.x) << 2;
    float4 v = *reinterpret_cast<const float4*>(x + i);
    __half2* ph = reinterpret_cast<__half2*>(g_xh + i);
    ph[0] = __floats2half2_rn(v.x, v.y);
    ph[1] = __floats2half2_rn(v.z, v.w);
}

// ---------------- main GEMM ----------------
__global__ void __launch_bounds__(THREADS, 1)
bitnet_gemm_kernel(const int* __restrict__ qw, const float* __restrict__ scale,
                   const float* __restrict__ bias, float* __restrict__ out) {
    extern __shared__ char smem[];
    const uint32_t su = smem_u32(smem);

    const int tid = threadIdx.x, wid = tid >> 5, lane = tid & 31;
    const int cta = blockIdx.x;
    int n0, n_sz;
    if (cta < 96) { n0 = cta * 80; n_sz = 80; }
    else          { n0 = 7680 + (cta - 96) * 64; n_sz = 64; }

    if (wid >= 8) {
        // ================= PRODUCER (warps 8-11, 128 threads) =================
        const int ptid = tid - 256;
        const int w_kp = ptid & 7, w_row0 = ptid >> 3;
        const int nWr = n_sz >> 4;                 // 5 (BN=80) or 4 (BN=64)
        const int* wbase = qw + (size_t)n0 * K_DIM + w_kp * 8;
        int woff[5];
#pragma unroll
        for (int j = 0; j < 5; ++j) woff[j] = (w_row0 + 16 * j) * K_DIM;
        const int a_kc = ptid & 7, a_row0 = ptid >> 3;
        const __half* abase = g_xh + (size_t)a_row0 * K_DIM + a_kc * 8;
        const uint32_t ad0 = (uint32_t)(a_row0 * ROWB + a_kc * 16);

        uint32_t wreg[40];
        auto ldgW = [&](int k0) {
#pragma unroll
            for (int j = 0; j < 5; ++j) {
                if (j < nWr) {
                    const int* s = wbase + woff[j] + k0;
                    asm volatile("ld.global.cs.v4.u32 {%0,%1,%2,%3}, [%4];"
                        : "=r"(wreg[8*j]),   "=r"(wreg[8*j+1]),
                          "=r"(wreg[8*j+2]), "=r"(wreg[8*j+3]) : "l"(s));
                    asm volatile("ld.global.cs.v4.u32 {%0,%1,%2,%3}, [%4];"
                        : "=r"(wreg[8*j+4]), "=r"(wreg[8*j+5]),
                          "=r"(wreg[8*j+6]), "=r"(wreg[8*j+7]) : "l"(s + 4));
                }
            }
        };

        ldgW(0);
#pragma unroll 1
        for (int k = 0; k < KITERS; ++k) {
            const int s = k % RING;
            if (k >= RING) bar_sync_named(FREE0 + s);   // stage free
            const uint32_t st = su + (uint32_t)(s * STG);
#pragma unroll
            for (int j = 0; j < 16; ++j)
                cp16(st + ad0 + (uint32_t)(j * 16 * ROWB),
                     abase + (size_t)j * 16 * K_DIM + k * BK);
            CP_COMMIT();
            const uint32_t stB = st + A_BYTES;
#pragma unroll
            for (int j = 0; j < 5; ++j) {
                if (j < nWr) {
                    uint32_t p0 = w2h2(wreg[8*j],   wreg[8*j+1]);
                    uint32_t p1 = w2h2(wreg[8*j+2], wreg[8*j+3]);
                    uint32_t p2 = w2h2(wreg[8*j+4], wreg[8*j+5]);
                    uint32_t p3 = w2h2(wreg[8*j+6], wreg[8*j+7]);
                    asm volatile("st.shared.v4.b32 [%0], {%1,%2,%3,%4};"
                        :: "r"(stB + (uint32_t)((w_row0 + 16*j) * ROWB + w_kp * 16)),
                           "r"(p0), "r"(p1), "r"(p2), "r"(p3) : "memory");
                }
            }
            if (k + 1 < KITERS) ldgW((k + 1) * BK);
            CP_WAIT0();
            __threadfence_block();
            bar_arrive_named(FULL0 + s);
        }
    } else {
        // ================= CONSUMER (warps 0-7, 256 threads) =================
        const int warp_m = wid & 3;        // 4 m-groups, 64 rows each
        const int warp_n = wid >> 2;       // 2 n-groups, 40 cols each
        const int nbase = warp_n * 40;
        int ntiles = (n_sz - nbase) >> 3;
        if (ntiles > 5) ntiles = 5;
        if (ntiles < 0) ntiles = 0;
        const bool full = (ntiles == 5);

        const uint32_t a_off = (uint32_t)((warp_m * 64 + (lane & 15)) * ROWB +
                                          ((lane >> 4) << 4));
        const uint32_t b_off4 = (uint32_t)((nbase + ((lane >> 4) << 3) + (lane & 7)) * ROWB +
                                           (((lane >> 3) & 1) << 4));
        const uint32_t b_off2 = (uint32_t)((nbase + 32 + (lane & 7)) * ROWB +
                                           (((lane >> 3) & 1) << 4));
        const uint32_t b_offs = (uint32_t)((nbase + (lane & 7)) * ROWB +
                                           (((lane >> 3) & 1) << 4));

        float acc[4][5][4];
#pragma unroll
        for (int mt = 0; mt < 4; ++mt)
#pragma unroll
            for (int nt = 0; nt < 5; ++nt)
#pragma unroll
                for (int r = 0; r < 4; ++r) acc[mt][nt][r] = 0.0f;

        uint32_t af[2][4][4], bf[2][5][2];

        auto load_frags = [&](uint32_t stA, uint32_t stB, int ks, int buf) {
            const uint32_t ksb = (uint32_t)(ks * 32);
            if (full) {
                ldsm4(&bf[buf][0][0], stB + b_off4 + ksb);
                ldsm4(&bf[buf][2][0], stB + b_off4 + 16 * ROWB + ksb);
                ldsm2(&bf[buf][4][0], stB + b_off2 + ksb);
            } else {
#pragma unroll
                for (int nt = 0; nt < 5; ++nt)
                    if (nt < ntiles)
                        ldsm2(&bf[buf][nt][0],
                              stB + b_offs + (uint32_t)(nt * 8 * ROWB) + ksb);
            }
#pragma unroll
            for (int mt = 0; mt < 4; ++mt)
                ldsm4(af[buf][mt], stA + a_off + (uint32_t)(mt * 16 * ROWB) + ksb);
        };

        // prime: wait stage 0 full, load its first frags
        bar_sync_named(FULL0 + 0);
        load_frags(su, su + A_BYTES, 0, 0);

#pragma unroll 1
        for (int k = 0; k < KITERS; ++k) {
            const int s = k % RING;
            const uint32_t stA = su + (uint32_t)(s * STG);
            const uint32_t stB = stA + A_BYTES;
#pragma unroll
            for (int ks = 0; ks < 4; ++ks) {
                const int buf = ks & 1;
                if (ks < 3) {
                    load_frags(stA, stB, ks + 1, buf ^ 1);
                } else if (k + 1 < KITERS) {
                    const int s2 = (k + 1) % RING;
                    bar_sync_named(FULL0 + s2);         // usually already passed
                    const uint32_t nA = su + (uint32_t)(s2 * STG);
                    load_frags(nA, nA + A_BYTES, 0, buf ^ 1);
                }
#pragma unroll
                for (int mt = 0; mt < 4; ++mt)
#pragma unroll
                    for (int nt = 0; nt < 5; ++nt)
                        if (nt < ntiles)
                            mma_f16(acc[mt][nt], af[buf][mt], bf[buf][nt]);
            }
            if (k < KITERS - RING) bar_arrive_named(FREE0 + s);
        }

        // ---- epilogue: scale/bias + store ----
        const int row_base = warp_m * 64 + (lane >> 2);
        const int col_base = n0 + nbase + ((lane & 3) << 1);
#pragma unroll
        for (int mt = 0; mt < 4; ++mt) {
#pragma unroll
            for (int nt = 0; nt < 5; ++nt) {
                if (nt < ntiles) {
                    int col = col_base + nt * 8;
                    float2 sc = *reinterpret_cast<const float2*>(scale + col);
                    float2 bs = *reinterpret_cast<const float2*>(bias + col);
                    int r0 = row_base + mt * 16;
                    float2 o0, o1;
                    o0.x = acc[mt][nt][0] * sc.x + bs.x;
                    o0.y = acc[mt][nt][1] * sc.y + bs.y;
                    o1.x = acc[mt][nt][2] * sc.x + bs.x;
                    o1.y = acc[mt][nt][3] * sc.y + bs.y;
                    *reinterpret_cast<float2*>(out + (size_t)r0 * N_DIM + col) = o0;
                    *reinterpret_cast<float2*>(out + (size_t)(r0 + 8) * N_DIM + col) = o1;
                }
            }
        }
    }
}

// ---------------- launch ----------------
extern "C" void kernel_launch(void* const* d_in, const int* in_sizes, int n_in,
                              void* d_out, int out_size) {
    const float* x = nullptr; const int* qw = nullptr;
    const float* scale = nullptr; const float* bias = nullptr;
    for (int i = 0; i < n_in; ++i) {
        if (in_sizes[i] == M_TOK * K_DIM) x = (const float*)d_in[i];
        else if (in_sizes[i] == N_DIM * K_DIM) qw = (const int*)d_in[i];
        else if (in_sizes[i] == N_DIM) {
            if (!scale) scale = (const float*)d_in[i];
            else bias = (const float*)d_in[i];
        }
    }
    float* out = (float*)d_out;

    cudaFuncSetAttribute(bitnet_gemm_kernel,
                         cudaFuncAttributeMaxDynamicSharedMemorySize, SMEM_ALLOC);

    conv_x_kernel<<<(M_TOK * K_DIM) / (256 * 4), 256>>>(x);
    bitnet_gemm_kernel<<<GRID, THREADS, SMEM_ALLOC>>>(qw, scale, bias, out);
}